// round 1
// baseline (speedup 1.0000x reference)
#include <cuda_runtime.h>
#include <cuda_bf16.h>
#include <math_constants.h>

#define BATCH 2048
#define TLEN  4096
#define NSIG  7
#define PRED  64

__constant__ float c_lrs[NSIG] = {0.01f, 0.08f, 0.1f, 0.15f, 0.2f, 0.25f, 1.0f};

// Scratch (static __device__ — no allocations allowed)
__device__ float g_errs[BATCH * NSIG];
__device__ float g_levels[BATCH * NSIG];
__device__ int   g_bestRow[BATCH];
__device__ int   g_sigIdx[BATCH];
__device__ float g_filt[(size_t)BATCH * TLEN];   // 32 MB

// ---------------------------------------------------------------------------
// K1: one thread per (row, sigma). Sequential EWMA; clip dropped (identity).
// err accumulated in 4 partials to keep summation error ~1e-6.
// ---------------------------------------------------------------------------
__global__ void scan_kernel(const float* __restrict__ data) {
    int gid = blockIdx.x * blockDim.x + threadIdx.x;
    if (gid >= BATCH * NSIG) return;
    int b = gid / NSIG;
    int s = gid - b * NSIG;
    float sigma = c_lrs[s];

    const float4* row = (const float4*)(data + (size_t)b * TLEN);
    float level = __ldg(data + (size_t)b * TLEN);   // y[0]
    float e0 = 0.f, e1 = 0.f, e2 = 0.f, e3 = 0.f;

#pragma unroll 4
    for (int i = 0; i < TLEN / 4; i++) {
        float4 y = __ldg(&row[i]);
        float d0 = y.x - level; e0 = fmaf(d0, d0, e0); level = fmaf(sigma, d0, level);
        float d1 = y.y - level; e1 = fmaf(d1, d1, e1); level = fmaf(sigma, d1, level);
        float d2 = y.z - level; e2 = fmaf(d2, d2, e2); level = fmaf(sigma, d2, level);
        float d3 = y.w - level; e3 = fmaf(d3, d3, e3); level = fmaf(sigma, d3, level);
    }
    g_errs[gid]   = ((e0 + e1) + (e2 + e3)) * (1.0f / (float)TLEN);
    g_levels[gid] = level;
}

// ---------------------------------------------------------------------------
// K2: per-row argmin over 7 sigmas (first-min), then running strict-< prefix
// min over rows (prefer-left on ties) via warp-shuffle scan.
// ---------------------------------------------------------------------------
__global__ void pick_kernel() {
    __shared__ float s_min[BATCH];
    __shared__ int   s_idx[BATCH];
    int tid = threadIdx.x;

    for (int b = tid; b < BATCH; b += blockDim.x) {
        const float* e = g_errs + b * NSIG;
        float best = e[0]; int bi = 0;
#pragma unroll
        for (int s = 1; s < NSIG; s++) {
            float v = e[s];
            if (v < best) { best = v; bi = s; }     // strict < => first min kept
        }
        s_min[b] = best; s_idx[b] = bi;
    }
    __syncthreads();

    if (tid < 32) {
        int lane = tid;
        float carryV = CUDART_INF_F;
        int   carryR = 0;
        for (int c = 0; c < BATCH / 32; c++) {
            int b = c * 32 + lane;
            float v = s_min[b];
            int   r = b;
            // inclusive prefix-min, prefer-left on ties
#pragma unroll
            for (int off = 1; off < 32; off <<= 1) {
                float pv = __shfl_up_sync(0xffffffffu, v, off);
                int   pr = __shfl_up_sync(0xffffffffu, r, off);
                if (lane >= off && !(v < pv)) { v = pv; r = pr; }
            }
            // fold in carry from previous chunks (carry wins unless strictly beaten)
            if (!(v < carryV)) { v = carryV; r = carryR; }
            g_bestRow[b] = r;
            g_sigIdx[b]  = s_idx[r];
            carryV = __shfl_sync(0xffffffffu, v, 31);
            carryR = __shfl_sync(0xffffffffu, r, 31);
        }
    }
}

// ---------------------------------------------------------------------------
// K3a: recompute the filtered series only for rows that are ever "best"
// (bestRow[r] == r). Blocked linear recurrence: chain = 1 FFMA per 4 steps.
//   h1..h4 = Horner prefix of y with factor a (off-chain)
//   level_{t+j} = a^j * level_t + sigma * h_j
// ---------------------------------------------------------------------------
__global__ void filt_kernel(const float* __restrict__ data) {
    int r = blockIdx.x;
    if (g_bestRow[r] != r) return;
    if (threadIdx.x != 0) return;

    float sigma = c_lrs[g_sigIdx[r]];
    float a  = 1.0f - sigma;
    float a2 = a * a;
    float a3 = a2 * a;
    float a4 = a2 * a2;

    const float4* row = (const float4*)(data + (size_t)r * TLEN);
    float4*       out = (float4*)(g_filt + (size_t)r * TLEN);
    float L = __ldg(data + (size_t)r * TLEN);   // y[0]

#pragma unroll 4
    for (int i = 0; i < TLEN / 4; i++) {
        float4 y = __ldg(&row[i]);
        float h1 = y.x;
        float h2 = fmaf(a, h1, y.y);
        float h3 = fmaf(a, h2, y.z);
        float h4 = fmaf(a, h3, y.w);
        float p1 = sigma * h1;
        float p2 = sigma * h2;
        float p3 = sigma * h3;
        float p4 = sigma * h4;
        float l1 = fmaf(a,  L, p1);
        float l2 = fmaf(a2, L, p2);
        float l3 = fmaf(a3, L, p3);
        float l4 = fmaf(a4, L, p4);      // the only on-chain op
        out[i] = make_float4(L, l1, l2, l3);   // filt is the PRIOR level
        L = l4;
    }
}

// ---------------------------------------------------------------------------
// K3b: out[b][t] = data[b][t] - filt[bestRow[b]][t]   (pure bandwidth)
// ---------------------------------------------------------------------------
__global__ void diff_kernel(const float* __restrict__ data, float* __restrict__ out) {
    int i = blockIdx.x * blockDim.x + threadIdx.x;   // float4 index
    const int rowq = TLEN / 4;
    if (i >= BATCH * rowq) return;
    int b = i / rowq;
    int c = i - b * rowq;
    int r = g_bestRow[b];
    float4 d = __ldg((const float4*)data + i);
    float4 f = __ldg((const float4*)g_filt + (size_t)r * rowq + c);
    float4 o;
    o.x = d.x - f.x; o.y = d.y - f.y; o.z = d.z - f.z; o.w = d.w - f.w;
    ((float4*)out)[i] = o;
}

// ---------------------------------------------------------------------------
// K4: preds[b][0..63] = levels[b][sigIdx[b]]
// ---------------------------------------------------------------------------
__global__ void preds_kernel(float* __restrict__ out) {
    int i = blockIdx.x * blockDim.x + threadIdx.x;
    if (i >= BATCH * PRED) return;
    int b = i >> 6;
    out[(size_t)BATCH * TLEN + i] = g_levels[b * NSIG + g_sigIdx[b]];
}

// ---------------------------------------------------------------------------
extern "C" void kernel_launch(void* const* d_in, const int* in_sizes, int n_in,
                              void* d_out, int out_size) {
    const float* data = (const float*)d_in[0];
    float* out = (float*)d_out;

    {
        int n = BATCH * NSIG;
        scan_kernel<<<(n + 255) / 256, 256>>>(data);
    }
    pick_kernel<<<1, 256>>>();
    filt_kernel<<<BATCH, 32>>>(data);
    {
        int n = BATCH * (TLEN / 4);
        diff_kernel<<<(n + 255) / 256, 256>>>(data, out);
    }
    {
        int n = BATCH * PRED;
        preds_kernel<<<(n + 255) / 256, 256>>>(out);
    }
}

// round 3
// speedup vs baseline: 2.6840x; 2.6840x over previous
#include <cuda_runtime.h>
#include <cuda_bf16.h>
#include <math_constants.h>

#define BATCH 2048
#define TLEN  4096
#define NSIG  7
#define PRED  64

__constant__ float c_lrs[NSIG] = {0.01f, 0.08f, 0.1f, 0.15f, 0.2f, 0.25f, 1.0f};

// Scratch (static __device__ — no allocations allowed)
__device__ float g_errs[BATCH * NSIG];
__device__ float g_levels[BATCH * NSIG];
__device__ int   g_bestRow[BATCH];
__device__ int   g_sigIdx[BATCH];
__device__ float g_filt[(size_t)BATCH * TLEN];   // 32 MB

// ---------------------------------------------------------------------------
// K1: one block (64 threads) per row; all 7 sigmas.
// Linear recurrence L' = a*L + sigma*y decomposed as a chunked scan:
//   pass1: per-thread transfer (A = a^64, C = sigma * Horner(y))  [off-chain]
//   scan : Hillis-Steele over 64 chunk transfers
//   pass2: local 64-step error accumulation from the chunk entry level
// ---------------------------------------------------------------------------
__global__ void __launch_bounds__(64) scan_all_kernel(const float* __restrict__ data) {
    constexpr int TPB = 64;
    constexpr int EPT = TLEN / TPB;       // 64 elements per thread
    __shared__ float sA[TPB], sC[TPB], sRed[TPB];
    __shared__ float s_y0;

    int r = blockIdx.x;
    int t = threadIdx.x;

    const float4* row = (const float4*)(data + (size_t)r * TLEN);
    float4 v[EPT / 4];                    // 64 floats in registers
#pragma unroll
    for (int i = 0; i < EPT / 4; i++) v[i] = __ldg(&row[t * (EPT / 4) + i]);

    if (t == 0) s_y0 = v[0].x;
    __syncthreads();
    float y0 = s_y0;

    for (int s = 0; s < NSIG; s++) {
        float sigma = c_lrs[s];
        float a = 1.0f - sigma;

        // pass1: Horner prefix of this chunk
        float H = 0.0f;
#pragma unroll
        for (int i = 0; i < EPT / 4; i++) {
            H = fmaf(a, H, v[i].x); H = fmaf(a, H, v[i].y);
            H = fmaf(a, H, v[i].z); H = fmaf(a, H, v[i].w);
        }
        float A = a;                       // a^64 via 6 squarings
        A *= A; A *= A; A *= A; A *= A; A *= A; A *= A;
        float C = sigma * H;

        // inclusive scan of transfers (prev-then-self composition)
        sA[t] = A; sC[t] = C;
        __syncthreads();
#pragma unroll
        for (int off = 1; off < TPB; off <<= 1) {
            float pa = 1.0f, pc = 0.0f;
            if (t >= off) { pa = sA[t - off]; pc = sC[t - off]; }
            __syncthreads();
            if (t >= off) { sC[t] = fmaf(sA[t], pc, sC[t]); sA[t] *= pa; }
            __syncthreads();
        }
        float Lent = (t == 0) ? y0 : fmaf(sA[t - 1], y0, sC[t - 1]);

        // pass2: local error accumulation
        float L = Lent;
        float e0 = 0.f, e1 = 0.f, e2 = 0.f, e3 = 0.f;
#pragma unroll
        for (int i = 0; i < EPT / 4; i++) {
            float d;
            d = v[i].x - L; e0 = fmaf(d, d, e0); L = fmaf(sigma, d, L);
            d = v[i].y - L; e1 = fmaf(d, d, e1); L = fmaf(sigma, d, L);
            d = v[i].z - L; e2 = fmaf(d, d, e2); L = fmaf(sigma, d, L);
            d = v[i].w - L; e3 = fmaf(d, d, e3); L = fmaf(sigma, d, L);
        }
        float err = (e0 + e1) + (e2 + e3);

        if (t == TPB - 1) g_levels[r * NSIG + s] = L;

        // reduce 64 partial errors
        sRed[t] = err;
        __syncthreads();
        if (t < 32) {
            float x = sRed[t] + sRed[t + 32];
#pragma unroll
            for (int off = 16; off > 0; off >>= 1)
                x += __shfl_down_sync(0xffffffffu, x, off);
            if (t == 0) g_errs[r * NSIG + s] = x * (1.0f / (float)TLEN);
        }
        __syncthreads();   // protects sA/sC/sRed before next sigma
    }
}

// ---------------------------------------------------------------------------
// K2: per-row argmin over 7 sigmas (first-min), then strict-< running prefix
// min over rows (prefer-left on ties) via warp-shuffle scan.
// ---------------------------------------------------------------------------
__global__ void pick_kernel() {
    __shared__ float s_min[BATCH];
    __shared__ int   s_idx[BATCH];
    int tid = threadIdx.x;

    for (int b = tid; b < BATCH; b += blockDim.x) {
        const float* e = g_errs + b * NSIG;
        float best = e[0]; int bi = 0;
#pragma unroll
        for (int s = 1; s < NSIG; s++) {
            float v = e[s];
            if (v < best) { best = v; bi = s; }
        }
        s_min[b] = best; s_idx[b] = bi;
    }
    __syncthreads();

    if (tid < 32) {
        int lane = tid;
        float carryV = CUDART_INF_F;
        int   carryR = 0;
        for (int c = 0; c < BATCH / 32; c++) {
            int b = c * 32 + lane;
            float v = s_min[b];
            int   r = b;
#pragma unroll
            for (int off = 1; off < 32; off <<= 1) {
                float pv = __shfl_up_sync(0xffffffffu, v, off);
                int   pr = __shfl_up_sync(0xffffffffu, r, off);
                if (lane >= off && !(v < pv)) { v = pv; r = pr; }
            }
            if (!(v < carryV)) { v = carryV; r = carryR; }
            g_bestRow[b] = r;
            g_sigIdx[b]  = s_idx[r];
            carryV = __shfl_sync(0xffffffffu, v, 31);
            carryR = __shfl_sync(0xffffffffu, r, 31);
        }
    }
}

// ---------------------------------------------------------------------------
// K3a: recompute & store the filtered series only for rows that are ever
// "best" (bestRow[r] == r), using the same chunked-scan decomposition with
// 128 threads (32 elements each). filt[t] is the PRIOR level.
// ---------------------------------------------------------------------------
__global__ void __launch_bounds__(128) filt_kernel(const float* __restrict__ data) {
    constexpr int TPB = 128;
    constexpr int EPT = TLEN / TPB;       // 32 elements per thread
    __shared__ float sA[TPB], sC[TPB];
    __shared__ float s_y0;

    int r = blockIdx.x;
    if (g_bestRow[r] != r) return;        // uniform across block
    int t = threadIdx.x;

    float sigma = c_lrs[g_sigIdx[r]];
    float a = 1.0f - sigma;

    const float4* row = (const float4*)(data + (size_t)r * TLEN);
    float4 v[EPT / 4];                    // 32 floats
#pragma unroll
    for (int i = 0; i < EPT / 4; i++) v[i] = __ldg(&row[t * (EPT / 4) + i]);

    if (t == 0) s_y0 = v[0].x;
    __syncthreads();
    float y0 = s_y0;

    float H = 0.0f;
#pragma unroll
    for (int i = 0; i < EPT / 4; i++) {
        H = fmaf(a, H, v[i].x); H = fmaf(a, H, v[i].y);
        H = fmaf(a, H, v[i].z); H = fmaf(a, H, v[i].w);
    }
    float A = a;                           // a^32 via 5 squarings
    A *= A; A *= A; A *= A; A *= A; A *= A;
    float C = sigma * H;

    sA[t] = A; sC[t] = C;
    __syncthreads();
#pragma unroll
    for (int off = 1; off < TPB; off <<= 1) {
        float pa = 1.0f, pc = 0.0f;
        if (t >= off) { pa = sA[t - off]; pc = sC[t - off]; }
        __syncthreads();
        if (t >= off) { sC[t] = fmaf(sA[t], pc, sC[t]); sA[t] *= pa; }
        __syncthreads();
    }
    float L = (t == 0) ? y0 : fmaf(sA[t - 1], y0, sC[t - 1]);

    float4* out = (float4*)(g_filt + (size_t)r * TLEN) + t * (EPT / 4);
#pragma unroll
    for (int i = 0; i < EPT / 4; i++) {
        float4 y = v[i];
        float4 f;
        f.x = L; L = fmaf(sigma, y.x - L, L);
        f.y = L; L = fmaf(sigma, y.y - L, L);
        f.z = L; L = fmaf(sigma, y.z - L, L);
        f.w = L; L = fmaf(sigma, y.w - L, L);
        out[i] = f;
    }
}

// ---------------------------------------------------------------------------
// K3b: out[b][t] = data[b][t] - filt[bestRow[b]][t]   (pure bandwidth)
// 2 float4 per thread for extra MLP; per-iteration guard (no early return)
// so both loads issue back-to-back.
// ---------------------------------------------------------------------------
__global__ void __launch_bounds__(256) diff_kernel(const float* __restrict__ data,
                                                   float* __restrict__ out) {
    const int rowq = TLEN / 4;
    int base = (blockIdx.x * blockDim.x + threadIdx.x) * 2;
#pragma unroll
    for (int k = 0; k < 2; k++) {
        int i = base + k;
        if (i < BATCH * rowq) {
            int b = i / rowq;
            int c = i - b * rowq;
            int r = g_bestRow[b];
            float4 d = __ldg((const float4*)data + i);
            float4 f = __ldg((const float4*)g_filt + (size_t)r * rowq + c);
            float4 o;
            o.x = d.x - f.x; o.y = d.y - f.y; o.z = d.z - f.z; o.w = d.w - f.w;
            ((float4*)out)[i] = o;
        }
    }
}

// ---------------------------------------------------------------------------
// K4: preds[b][0..63] = levels[b][sigIdx[b]]
// ---------------------------------------------------------------------------
__global__ void preds_kernel(float* __restrict__ out) {
    int i = blockIdx.x * blockDim.x + threadIdx.x;
    if (i >= BATCH * PRED) return;
    int b = i >> 6;
    out[(size_t)BATCH * TLEN + i] = g_levels[b * NSIG + g_sigIdx[b]];
}

// ---------------------------------------------------------------------------
extern "C" void kernel_launch(void* const* d_in, const int* in_sizes, int n_in,
                              void* d_out, int out_size) {
    const float* data = (const float*)d_in[0];
    float* out = (float*)d_out;

    scan_all_kernel<<<BATCH, 64>>>(data);
    pick_kernel<<<1, 256>>>();
    filt_kernel<<<BATCH, 128>>>(data);
    {
        int nq = BATCH * (TLEN / 4);             // float4 count
        int threads = 256;
        int blocks = (nq / 2 + threads - 1) / threads;
        diff_kernel<<<blocks, threads>>>(data, out);
    }
    {
        int n = BATCH * PRED;
        preds_kernel<<<(n + 255) / 256, 256>>>(out);
    }
}

// round 4
// speedup vs baseline: 3.9945x; 1.4883x over previous
#include <cuda_runtime.h>
#include <cuda_bf16.h>
#include <math_constants.h>

#define BATCH 2048
#define TLEN  4096
#define NSIG  7
#define PRED  64

typedef unsigned long long ull;

__constant__ float c_lrs[NSIG] = {0.01f, 0.08f, 0.1f, 0.15f, 0.2f, 0.25f, 1.0f};

// Scratch (static __device__ — no allocations allowed)
__device__ float g_errs[BATCH * NSIG];
__device__ float g_levels[BATCH * NSIG];
__device__ int   g_bestRow[BATCH];
__device__ int   g_sigIdx[BATCH];
__device__ float g_filt[(size_t)BATCH * TLEN];   // 32 MB

// ---- packed f32x2 helpers (Blackwell; PTX-only path) -----------------------
__device__ __forceinline__ ull pack2(float lo, float hi) {
    ull r; asm("mov.b64 %0, {%1, %2};" : "=l"(r) : "f"(lo), "f"(hi)); return r;
}
__device__ __forceinline__ void unpack2(ull v, float& lo, float& hi) {
    asm("mov.b64 {%0, %1}, %2;" : "=f"(lo), "=f"(hi) : "l"(v));
}
__device__ __forceinline__ ull ffma2(ull a, ull b, ull c) {
    ull d; asm("fma.rn.f32x2 %0, %1, %2, %3;" : "=l"(d) : "l"(a), "l"(b), "l"(c)); return d;
}
__device__ __forceinline__ ull fmul2(ull a, ull b) {
    ull d; asm("mul.rn.f32x2 %0, %1, %2;" : "=l"(d) : "l"(a), "l"(b)); return d;
}

// ---------------------------------------------------------------------------
// K1: one block (64 threads) per row. 6 sigmas packed into 3 f32x2 pairs;
// sigma=1.0 handled analytically (filt[t] = y[t-1]).
// Linear recurrence L' = a*L + sigma*y as chunked scan:
//   phase1: per-thread transfer (A = a^64, C = sigma*Horner) for 3 pairs
//   scan  : warp-shuffle inclusive scan + 1 cross-warp fix-up
//   phase2: local error accumulation from chunk entry level
// ---------------------------------------------------------------------------
__global__ void __launch_bounds__(64) scan_all_kernel(const float* __restrict__ data) {
    constexpr int TPB = 64;
    __shared__ float sLast[TPB];
    __shared__ float s_y0;
    __shared__ ull   sTotA[3], sTotC[3];
    __shared__ float sE[NSIG][TPB];

    int r = blockIdx.x;
    int t = threadIdx.x;
    int lane = t & 31;
    int w = t >> 5;

    const float4* row = (const float4*)(data + (size_t)r * TLEN);
    float4 v[16];                          // 64 floats in registers
#pragma unroll
    for (int i = 0; i < 16; i++) v[i] = __ldg(&row[t * 16 + i]);

    sLast[t] = v[15].w;
    if (t == 0) s_y0 = v[0].x;
    __syncthreads();
    float y0 = s_y0;
    float yprev = (t == 0) ? v[0].x : sLast[t - 1];

    ull SIG[3], A1[3];
    SIG[0] = pack2(0.01f, 0.08f); SIG[1] = pack2(0.10f, 0.15f); SIG[2] = pack2(0.20f, 0.25f);
    A1[0]  = pack2(1.0f - 0.01f, 1.0f - 0.08f);
    A1[1]  = pack2(1.0f - 0.10f, 1.0f - 0.15f);
    A1[2]  = pack2(1.0f - 0.20f, 1.0f - 0.25f);

    // --- phase1: Horner prefix per pair --------------------------------------
    ull H[3] = {0ull, 0ull, 0ull};         // pack2(0,0) == 0
#pragma unroll
    for (int i = 0; i < 16; i++) {
#define P1STEP(Y) { ull y2 = pack2((Y), (Y));            \
        H[0] = ffma2(A1[0], H[0], y2);                   \
        H[1] = ffma2(A1[1], H[1], y2);                   \
        H[2] = ffma2(A1[2], H[2], y2); }
        P1STEP(v[i].x) P1STEP(v[i].y) P1STEP(v[i].z) P1STEP(v[i].w)
#undef P1STEP
    }
    ull A[3], C[3];
#pragma unroll
    for (int p = 0; p < 3; p++) {
        ull a = A1[p];                     // a^64 via 6 packed squarings
        a = fmul2(a, a); a = fmul2(a, a); a = fmul2(a, a);
        a = fmul2(a, a); a = fmul2(a, a); a = fmul2(a, a);
        A[p] = a;
        C[p] = fmul2(SIG[p], H[p]);
    }

    // --- inclusive warp-shuffle scan of transfers ----------------------------
#pragma unroll
    for (int p = 0; p < 3; p++) {
#pragma unroll
        for (int off = 1; off < 32; off <<= 1) {
            ull pa = __shfl_up_sync(0xffffffffu, A[p], off);
            ull pc = __shfl_up_sync(0xffffffffu, C[p], off);
            if (lane >= off) { C[p] = ffma2(A[p], pc, C[p]); A[p] = fmul2(A[p], pa); }
        }
    }
    if (t == 31) {
#pragma unroll
        for (int p = 0; p < 3; p++) { sTotA[p] = A[p]; sTotC[p] = C[p]; }
    }
    __syncthreads();

    ull y0_2 = pack2(y0, y0);
    ull Lent[3];
#pragma unroll
    for (int p = 0; p < 3; p++) {
        if (w == 1) {                      // compose warp0 total in front
            C[p] = ffma2(A[p], sTotC[p], C[p]);
            A[p] = fmul2(A[p], sTotA[p]);
        }
        ull ea = __shfl_up_sync(0xffffffffu, A[p], 1);
        ull ec = __shfl_up_sync(0xffffffffu, C[p], 1);
        if (t == 0)            Lent[p] = y0_2;
        else if (lane == 0)    Lent[p] = ffma2(sTotA[p], y0_2, sTotC[p]);  // w==1 lane0
        else                   Lent[p] = ffma2(ea, y0_2, ec);
    }

    // --- phase2: local error accumulation ------------------------------------
    ull L[3] = {Lent[0], Lent[1], Lent[2]};
    ull E[3] = {0ull, 0ull, 0ull};
    ull NEG1 = pack2(-1.0f, -1.0f);
    float e6 = 0.0f;
    float yp = yprev;
#pragma unroll
    for (int i = 0; i < 16; i++) {
#define P2STEP(Y) { float yy = (Y); ull y2 = pack2(yy, yy);      \
        ull d0 = ffma2(L[0], NEG1, y2);                          \
        ull d1 = ffma2(L[1], NEG1, y2);                          \
        ull d2 = ffma2(L[2], NEG1, y2);                          \
        E[0] = ffma2(d0, d0, E[0]); L[0] = ffma2(SIG[0], d0, L[0]); \
        E[1] = ffma2(d1, d1, E[1]); L[1] = ffma2(SIG[1], d1, L[1]); \
        E[2] = ffma2(d2, d2, E[2]); L[2] = ffma2(SIG[2], d2, L[2]); \
        float d6 = yy - yp; e6 = fmaf(d6, d6, e6); yp = yy; }
        P2STEP(v[i].x) P2STEP(v[i].y) P2STEP(v[i].z) P2STEP(v[i].w)
#undef P2STEP
    }

    float ev[NSIG];
    unpack2(E[0], ev[0], ev[1]);
    unpack2(E[1], ev[2], ev[3]);
    unpack2(E[2], ev[4], ev[5]);
    ev[6] = e6;
#pragma unroll
    for (int q = 0; q < NSIG; q++) sE[q][t] = ev[q];

    if (t == TPB - 1) {                    // final levels (thread 63's exit state)
        float l0, l1; unpack2(L[0], l0, l1);
        g_levels[r * NSIG + 0] = l0; g_levels[r * NSIG + 1] = l1;
        unpack2(L[1], l0, l1);
        g_levels[r * NSIG + 2] = l0; g_levels[r * NSIG + 3] = l1;
        unpack2(L[2], l0, l1);
        g_levels[r * NSIG + 4] = l0; g_levels[r * NSIG + 5] = l1;
        g_levels[r * NSIG + 6] = v[15].w;  // sigma=1: level = y[T-1]
    }
    __syncthreads();

    if (t < 32) {
#pragma unroll
        for (int q = 0; q < NSIG; q++) {
            float x = sE[q][t] + sE[q][t + 32];
#pragma unroll
            for (int off = 16; off > 0; off >>= 1)
                x += __shfl_down_sync(0xffffffffu, x, off);
            if (t == 0) g_errs[r * NSIG + q] = x * (1.0f / (float)TLEN);
        }
    }
}

// ---------------------------------------------------------------------------
// K2: per-row argmin over 7 sigmas (first-min), then strict-< running prefix
// min over rows (prefer-left on ties) via warp-shuffle scan.
// ---------------------------------------------------------------------------
__global__ void pick_kernel() {
    __shared__ float s_min[BATCH];
    __shared__ int   s_idx[BATCH];
    int tid = threadIdx.x;

    for (int b = tid; b < BATCH; b += blockDim.x) {
        const float* e = g_errs + b * NSIG;
        float best = e[0]; int bi = 0;
#pragma unroll
        for (int s = 1; s < NSIG; s++) {
            float v = e[s];
            if (v < best) { best = v; bi = s; }
        }
        s_min[b] = best; s_idx[b] = bi;
    }
    __syncthreads();

    if (tid < 32) {
        int lane = tid;
        float carryV = CUDART_INF_F;
        int   carryR = 0;
        for (int c = 0; c < BATCH / 32; c++) {
            int b = c * 32 + lane;
            float v = s_min[b];
            int   r = b;
#pragma unroll
            for (int off = 1; off < 32; off <<= 1) {
                float pv = __shfl_up_sync(0xffffffffu, v, off);
                int   pr = __shfl_up_sync(0xffffffffu, r, off);
                if (lane >= off && !(v < pv)) { v = pv; r = pr; }
            }
            if (!(v < carryV)) { v = carryV; r = carryR; }
            g_bestRow[b] = r;
            g_sigIdx[b]  = s_idx[r];
            carryV = __shfl_sync(0xffffffffu, v, 31);
            carryR = __shfl_sync(0xffffffffu, r, 31);
        }
    }
}

// ---------------------------------------------------------------------------
// K3a: recompute & store the filtered series only for rows that are ever
// "best" (bestRow[r] == r); chunked scan, 128 threads. filt is PRIOR level.
// ---------------------------------------------------------------------------
__global__ void __launch_bounds__(128) filt_kernel(const float* __restrict__ data) {
    constexpr int TPB = 128;
    constexpr int EPT = TLEN / TPB;       // 32 elements per thread
    __shared__ float sA[TPB], sC[TPB];
    __shared__ float s_y0;

    int r = blockIdx.x;
    if (g_bestRow[r] != r) return;        // uniform across block
    int t = threadIdx.x;

    float sigma = c_lrs[g_sigIdx[r]];
    float a = 1.0f - sigma;

    const float4* row = (const float4*)(data + (size_t)r * TLEN);
    float4 v[EPT / 4];
#pragma unroll
    for (int i = 0; i < EPT / 4; i++) v[i] = __ldg(&row[t * (EPT / 4) + i]);

    if (t == 0) s_y0 = v[0].x;
    __syncthreads();
    float y0 = s_y0;

    float H = 0.0f;
#pragma unroll
    for (int i = 0; i < EPT / 4; i++) {
        H = fmaf(a, H, v[i].x); H = fmaf(a, H, v[i].y);
        H = fmaf(a, H, v[i].z); H = fmaf(a, H, v[i].w);
    }
    float A = a;                           // a^32 via 5 squarings
    A *= A; A *= A; A *= A; A *= A; A *= A;
    float C = sigma * H;

    sA[t] = A; sC[t] = C;
    __syncthreads();
#pragma unroll
    for (int off = 1; off < TPB; off <<= 1) {
        float pa = 1.0f, pc = 0.0f;
        if (t >= off) { pa = sA[t - off]; pc = sC[t - off]; }
        __syncthreads();
        if (t >= off) { sC[t] = fmaf(sA[t], pc, sC[t]); sA[t] *= pa; }
        __syncthreads();
    }
    float L = (t == 0) ? y0 : fmaf(sA[t - 1], y0, sC[t - 1]);

    float4* out = (float4*)(g_filt + (size_t)r * TLEN) + t * (EPT / 4);
#pragma unroll
    for (int i = 0; i < EPT / 4; i++) {
        float4 y = v[i];
        float4 f;
        f.x = L; L = fmaf(sigma, y.x - L, L);
        f.y = L; L = fmaf(sigma, y.y - L, L);
        f.z = L; L = fmaf(sigma, y.z - L, L);
        f.w = L; L = fmaf(sigma, y.w - L, L);
        out[i] = f;
    }
}

// ---------------------------------------------------------------------------
// K3b: out[b][t] = data[b][t] - filt[bestRow[b]][t]   (pure bandwidth)
// 1 float4/thread (best measured config); streaming hints on the
// read-once/write-once streams, cacheable loads for the ~11 hot filt rows.
// ---------------------------------------------------------------------------
__global__ void __launch_bounds__(256) diff_kernel(const float* __restrict__ data,
                                                   float* __restrict__ out) {
    const int rowq = TLEN / 4;
    int i = blockIdx.x * blockDim.x + threadIdx.x;
    if (i >= BATCH * rowq) return;
    int b = i / rowq;
    int c = i - b * rowq;
    int r = g_bestRow[b];
    float4 d = __ldcs((const float4*)data + i);
    float4 f = __ldg((const float4*)g_filt + (size_t)r * rowq + c);
    float4 o;
    o.x = d.x - f.x; o.y = d.y - f.y; o.z = d.z - f.z; o.w = d.w - f.w;
    __stcs((float4*)out + i, o);
}

// ---------------------------------------------------------------------------
// K4: preds[b][0..63] = levels[b][sigIdx[b]]
// ---------------------------------------------------------------------------
__global__ void preds_kernel(float* __restrict__ out) {
    int i = blockIdx.x * blockDim.x + threadIdx.x;
    if (i >= BATCH * PRED) return;
    int b = i >> 6;
    out[(size_t)BATCH * TLEN + i] = g_levels[b * NSIG + g_sigIdx[b]];
}

// ---------------------------------------------------------------------------
extern "C" void kernel_launch(void* const* d_in, const int* in_sizes, int n_in,
                              void* d_out, int out_size) {
    const float* data = (const float*)d_in[0];
    float* out = (float*)d_out;

    scan_all_kernel<<<BATCH, 64>>>(data);
    pick_kernel<<<1, 256>>>();
    filt_kernel<<<BATCH, 128>>>(data);
    {
        int nq = BATCH * (TLEN / 4);             // float4 count
        diff_kernel<<<(nq + 255) / 256, 256>>>(data, out);
    }
    {
        int n = BATCH * PRED;
        preds_kernel<<<(n + 255) / 256, 256>>>(out);
    }
}

// round 5
// speedup vs baseline: 4.0008x; 1.0016x over previous
#include <cuda_runtime.h>
#include <cuda_bf16.h>
#include <math_constants.h>

#define BATCH 2048
#define TLEN  4096
#define NSIG  7
#define PRED  64

typedef unsigned long long ull;

__constant__ float c_lrs[NSIG] = {0.01f, 0.08f, 0.1f, 0.15f, 0.2f, 0.25f, 1.0f};

// Scratch (static __device__ — no allocations allowed)
__device__ float g_errs[BATCH * NSIG];
__device__ float g_levels[BATCH * NSIG];
__device__ int   g_bestRow[BATCH];
__device__ int   g_sigIdx[BATCH];
__device__ float g_filt[(size_t)BATCH * TLEN];   // only ~log2(B) rows ever written

// ---- packed f32x2 helpers (Blackwell; PTX-only path) -----------------------
__device__ __forceinline__ ull pack2(float lo, float hi) {
    ull r; asm("mov.b64 %0, {%1, %2};" : "=l"(r) : "f"(lo), "f"(hi)); return r;
}
__device__ __forceinline__ void unpack2(ull v, float& lo, float& hi) {
    asm("mov.b64 {%0, %1}, %2;" : "=f"(lo), "=f"(hi) : "l"(v));
}
__device__ __forceinline__ ull ffma2(ull a, ull b, ull c) {
    ull d; asm("fma.rn.f32x2 %0, %1, %2, %3;" : "=l"(d) : "l"(a), "l"(b), "l"(c)); return d;
}
__device__ __forceinline__ ull fmul2(ull a, ull b) {
    ull d; asm("mul.rn.f32x2 %0, %1, %2;" : "=l"(d) : "l"(a), "l"(b)); return d;
}

// ---------------------------------------------------------------------------
// K1: one block (128 threads) per row; 32 elems/thread. 6 sigmas in 3 f32x2
// pairs; sigma=1.0 analytically (filt[t] = y[t-1]).
//   phase1: per-thread transfer (A = a^32, C = sigma*Horner)
//   scan  : warp-shuffle inclusive scan + 4-warp smem fix-up (2 syncs total)
//   phase2: local error accumulation from chunk entry level
// ---------------------------------------------------------------------------
__global__ void __launch_bounds__(128) scan_all_kernel(const float* __restrict__ data) {
    constexpr int TPB = 128;
    __shared__ float sLast[TPB];
    __shared__ float s_y0;
    __shared__ ull   sWA[4 * 3], sWC[4 * 3];
    __shared__ float sE[NSIG][TPB];

    int r = blockIdx.x;
    int t = threadIdx.x;
    int lane = t & 31;
    int w = t >> 5;

    const float4* row = (const float4*)(data + (size_t)r * TLEN);
    float4 v[8];                           // 32 floats in registers
#pragma unroll
    for (int i = 0; i < 8; i++) v[i] = __ldg(&row[t * 8 + i]);

    sLast[t] = v[7].w;
    if (t == 0) s_y0 = v[0].x;
    __syncthreads();
    float y0 = s_y0;
    float yprev = (t == 0) ? v[0].x : sLast[t - 1];

    ull SIG[3], A1[3];
    SIG[0] = pack2(0.01f, 0.08f); SIG[1] = pack2(0.10f, 0.15f); SIG[2] = pack2(0.20f, 0.25f);
    A1[0]  = pack2(1.0f - 0.01f, 1.0f - 0.08f);
    A1[1]  = pack2(1.0f - 0.10f, 1.0f - 0.15f);
    A1[2]  = pack2(1.0f - 0.20f, 1.0f - 0.25f);

    // --- phase1: Horner prefix per pair --------------------------------------
    ull H[3] = {0ull, 0ull, 0ull};
#pragma unroll
    for (int i = 0; i < 8; i++) {
#define P1STEP(Y) { ull y2 = pack2((Y), (Y));            \
        H[0] = ffma2(A1[0], H[0], y2);                   \
        H[1] = ffma2(A1[1], H[1], y2);                   \
        H[2] = ffma2(A1[2], H[2], y2); }
        P1STEP(v[i].x) P1STEP(v[i].y) P1STEP(v[i].z) P1STEP(v[i].w)
#undef P1STEP
    }
    ull A[3], C[3];
#pragma unroll
    for (int p = 0; p < 3; p++) {
        ull a = A1[p];                     // a^32 via 5 packed squarings
        a = fmul2(a, a); a = fmul2(a, a); a = fmul2(a, a);
        a = fmul2(a, a); a = fmul2(a, a);
        A[p] = a;
        C[p] = fmul2(SIG[p], H[p]);
    }

    // --- inclusive warp-shuffle scan + cross-warp fix-up ---------------------
#pragma unroll
    for (int p = 0; p < 3; p++) {
#pragma unroll
        for (int off = 1; off < 32; off <<= 1) {
            ull pa = __shfl_up_sync(0xffffffffu, A[p], off);
            ull pc = __shfl_up_sync(0xffffffffu, C[p], off);
            if (lane >= off) { C[p] = ffma2(A[p], pc, C[p]); A[p] = fmul2(A[p], pa); }
        }
        if (lane == 31) { sWA[w * 3 + p] = A[p]; sWC[w * 3 + p] = C[p]; }
    }
    __syncthreads();

    ull ONE2 = pack2(1.0f, 1.0f);
    ull y0_2 = pack2(y0, y0);
    ull Lent[3];
#pragma unroll
    for (int p = 0; p < 3; p++) {
        // transfer of all warps before w (applied first)
        ull pA = ONE2, pC = 0ull;
#pragma unroll
        for (int j = 0; j < 3; j++) {
            if (j < w) {
                pC = ffma2(sWA[j * 3 + p], pC, sWC[j * 3 + p]);
                pA = fmul2(sWA[j * 3 + p], pA);
            }
        }
        // in-warp exclusive transfer
        ull eA = __shfl_up_sync(0xffffffffu, A[p], 1);
        ull eC = __shfl_up_sync(0xffffffffu, C[p], 1);
        ull Aex, Cex;
        if (lane == 0) { Aex = pA; Cex = pC; }
        else           { Aex = fmul2(eA, pA); Cex = ffma2(eA, pC, eC); }
        Lent[p] = ffma2(Aex, y0_2, Cex);
    }

    // --- phase2: local error accumulation ------------------------------------
    ull L[3] = {Lent[0], Lent[1], Lent[2]};
    ull E[3] = {0ull, 0ull, 0ull};
    ull NEG1 = pack2(-1.0f, -1.0f);
    float e6 = 0.0f;
    float yp = yprev;
#pragma unroll
    for (int i = 0; i < 8; i++) {
#define P2STEP(Y) { float yy = (Y); ull y2 = pack2(yy, yy);      \
        ull d0 = ffma2(L[0], NEG1, y2);                          \
        ull d1 = ffma2(L[1], NEG1, y2);                          \
        ull d2 = ffma2(L[2], NEG1, y2);                          \
        E[0] = ffma2(d0, d0, E[0]); L[0] = ffma2(SIG[0], d0, L[0]); \
        E[1] = ffma2(d1, d1, E[1]); L[1] = ffma2(SIG[1], d1, L[1]); \
        E[2] = ffma2(d2, d2, E[2]); L[2] = ffma2(SIG[2], d2, L[2]); \
        float d6 = yy - yp; e6 = fmaf(d6, d6, e6); yp = yy; }
        P2STEP(v[i].x) P2STEP(v[i].y) P2STEP(v[i].z) P2STEP(v[i].w)
#undef P2STEP
    }

    float ev[NSIG];
    unpack2(E[0], ev[0], ev[1]);
    unpack2(E[1], ev[2], ev[3]);
    unpack2(E[2], ev[4], ev[5]);
    ev[6] = e6;
#pragma unroll
    for (int q = 0; q < NSIG; q++) sE[q][t] = ev[q];

    if (t == TPB - 1) {                    // final levels (last thread's exit state)
        float l0, l1; unpack2(L[0], l0, l1);
        g_levels[r * NSIG + 0] = l0; g_levels[r * NSIG + 1] = l1;
        unpack2(L[1], l0, l1);
        g_levels[r * NSIG + 2] = l0; g_levels[r * NSIG + 3] = l1;
        unpack2(L[2], l0, l1);
        g_levels[r * NSIG + 4] = l0; g_levels[r * NSIG + 5] = l1;
        g_levels[r * NSIG + 6] = v[7].w;   // sigma=1: level = y[T-1]
    }
    __syncthreads();

    if (t < 64) {
#pragma unroll
        for (int q = 0; q < NSIG; q++) sE[q][t] += sE[q][t + 64];
    }
    __syncthreads();
    if (t < 32) {
#pragma unroll
        for (int q = 0; q < NSIG; q++) {
            float x = sE[q][t] + sE[q][t + 32];
#pragma unroll
            for (int off = 16; off > 0; off >>= 1)
                x += __shfl_down_sync(0xffffffffu, x, off);
            if (t == 0) g_errs[r * NSIG + q] = x * (1.0f / (float)TLEN);
        }
    }
}

// ---------------------------------------------------------------------------
// K2: per-row argmin over 7 sigmas (first-min), then strict-< running prefix
// min over rows (prefer-left on ties) via warp-shuffle scan.
// ---------------------------------------------------------------------------
__global__ void pick_kernel() {
    __shared__ float s_min[BATCH];
    __shared__ int   s_idx[BATCH];
    int tid = threadIdx.x;

    for (int b = tid; b < BATCH; b += blockDim.x) {
        const float* e = g_errs + b * NSIG;
        float best = e[0]; int bi = 0;
#pragma unroll
        for (int s = 1; s < NSIG; s++) {
            float v = e[s];
            if (v < best) { best = v; bi = s; }
        }
        s_min[b] = best; s_idx[b] = bi;
    }
    __syncthreads();

    if (tid < 32) {
        int lane = tid;
        float carryV = CUDART_INF_F;
        int   carryR = 0;
        for (int c = 0; c < BATCH / 32; c++) {
            int b = c * 32 + lane;
            float v = s_min[b];
            int   r = b;
#pragma unroll
            for (int off = 1; off < 32; off <<= 1) {
                float pv = __shfl_up_sync(0xffffffffu, v, off);
                int   pr = __shfl_up_sync(0xffffffffu, r, off);
                if (lane >= off && !(v < pv)) { v = pv; r = pr; }
            }
            if (!(v < carryV)) { v = carryV; r = carryR; }
            g_bestRow[b] = r;
            g_sigIdx[b]  = s_idx[r];
            carryV = __shfl_sync(0xffffffffu, v, 31);
            carryR = __shfl_sync(0xffffffffu, r, 31);
        }
    }
}

// ---------------------------------------------------------------------------
// K3a: recompute & store the filtered series only for rows that are ever
// "best" (bestRow[r] == r); chunked scan, 128 threads. filt is PRIOR level.
// ---------------------------------------------------------------------------
__global__ void __launch_bounds__(128) filt_kernel(const float* __restrict__ data) {
    constexpr int TPB = 128;
    constexpr int EPT = TLEN / TPB;       // 32 elements per thread
    __shared__ float sA[TPB], sC[TPB];
    __shared__ float s_y0;

    int r = blockIdx.x;
    if (g_bestRow[r] != r) return;        // uniform across block
    int t = threadIdx.x;

    float sigma = c_lrs[g_sigIdx[r]];
    float a = 1.0f - sigma;

    const float4* row = (const float4*)(data + (size_t)r * TLEN);
    float4 v[EPT / 4];
#pragma unroll
    for (int i = 0; i < EPT / 4; i++) v[i] = __ldg(&row[t * (EPT / 4) + i]);

    if (t == 0) s_y0 = v[0].x;
    __syncthreads();
    float y0 = s_y0;

    float H = 0.0f;
#pragma unroll
    for (int i = 0; i < EPT / 4; i++) {
        H = fmaf(a, H, v[i].x); H = fmaf(a, H, v[i].y);
        H = fmaf(a, H, v[i].z); H = fmaf(a, H, v[i].w);
    }
    float A = a;                           // a^32 via 5 squarings
    A *= A; A *= A; A *= A; A *= A; A *= A;
    float C = sigma * H;

    sA[t] = A; sC[t] = C;
    __syncthreads();
#pragma unroll
    for (int off = 1; off < TPB; off <<= 1) {
        float pa = 1.0f, pc = 0.0f;
        if (t >= off) { pa = sA[t - off]; pc = sC[t - off]; }
        __syncthreads();
        if (t >= off) { sC[t] = fmaf(sA[t], pc, sC[t]); sA[t] *= pa; }
        __syncthreads();
    }
    float L = (t == 0) ? y0 : fmaf(sA[t - 1], y0, sC[t - 1]);

    float4* out = (float4*)(g_filt + (size_t)r * TLEN) + t * (EPT / 4);
#pragma unroll
    for (int i = 0; i < EPT / 4; i++) {
        float4 y = v[i];
        float4 f;
        f.x = L; L = fmaf(sigma, y.x - L, L);
        f.y = L; L = fmaf(sigma, y.y - L, L);
        f.z = L; L = fmaf(sigma, y.z - L, L);
        f.w = L; L = fmaf(sigma, y.w - L, L);
        out[i] = f;
    }
}

// ---------------------------------------------------------------------------
// K3b: out[b][t] = data[b][t] - filt[bestRow[b]][t]; first 32K threads also
// write the broadcast preds block (fused K4).
// ---------------------------------------------------------------------------
__global__ void __launch_bounds__(256) diff_kernel(const float* __restrict__ data,
                                                   float* __restrict__ out) {
    const int rowq = TLEN / 4;
    int i = blockIdx.x * blockDim.x + threadIdx.x;
    if (i < BATCH * rowq) {
        int b = i / rowq;
        int c = i - b * rowq;
        int r = g_bestRow[b];
        float4 d = __ldcs((const float4*)data + i);
        float4 f = __ldg((const float4*)g_filt + (size_t)r * rowq + c);
        float4 o;
        o.x = d.x - f.x; o.y = d.y - f.y; o.z = d.z - f.z; o.w = d.w - f.w;
        __stcs((float4*)out + i, o);
    }
    if (i < BATCH * (PRED / 4)) {          // preds: 16 float4 per row
        int b = i >> 4;
        float val = g_levels[b * NSIG + g_sigIdx[b]];
        float4 o = make_float4(val, val, val, val);
        __stcs((float4*)out + BATCH * rowq + i, o);
    }
}

// ---------------------------------------------------------------------------
extern "C" void kernel_launch(void* const* d_in, const int* in_sizes, int n_in,
                              void* d_out, int out_size) {
    const float* data = (const float*)d_in[0];
    float* out = (float*)d_out;

    scan_all_kernel<<<BATCH, 128>>>(data);
    pick_kernel<<<1, 256>>>();
    filt_kernel<<<BATCH, 128>>>(data);
    {
        int nq = BATCH * (TLEN / 4);             // float4 count
        diff_kernel<<<(nq + 255) / 256, 256>>>(data, out);
    }
}